// round 10
// baseline (speedup 1.0000x reference)
#include <cuda_runtime.h>
#include <cstdint>

#define SPLITS    4
#define NTHREADS  256
#define TOPN      64
#define CAP       1024
#define MAXB      128
#define T_INIT    6.0f

__device__ unsigned long long gCand[MAXB * CAP];
__device__ float gPart[MAXB * SPLITS];
__device__ int   gCnt[MAXB];
__device__ int   gDone[MAXB];

__device__ __forceinline__ uint32_t f2key(float x) {
    uint32_t u = __float_as_uint(x);
    return (u & 0x80000000u) ? ~u : (u | 0x80000000u);
}
__device__ __forceinline__ float key2f(uint32_t k) {
    uint32_t u = (k & 0x80000000u) ? (k & 0x7FFFFFFFu) : ~k;
    return __uint_as_float(u);
}
__device__ __forceinline__ float max4(float4 x) {
    return fmaxf(fmaxf(x.x, x.y), fmaxf(x.z, x.w));
}
__device__ __forceinline__ void pushg(float v, int idx, int row) {
    int p = atomicAdd(&gCnt[row], 1);
    if (p < CAP)
        gCand[row * CAP + p] =
            ((unsigned long long)f2key(v) << 32) | (uint32_t)(~(uint32_t)idx);
}
__device__ __forceinline__ void collect4g(float4 x, int base, float T, int row) {
    if (max4(x) >= T) {   // rarely taken (~0.5% of float4s)
        if (x.x >= T) pushg(x.x, base + 0, row);
        if (x.y >= T) pushg(x.y, base + 1, row);
        if (x.z >= T) pushg(x.z, base + 2, row);
        if (x.w >= T) pushg(x.w, base + 3, row);
    }
}

__global__ __launch_bounds__(NTHREADS, 6)
void sampler_kernel(const float* __restrict__ logits,
                    const int*   __restrict__ top_ks,
                    const float* __restrict__ top_ps,
                    const float* __restrict__ min_ps,
                    const float* __restrict__ uvec,
                    float* __restrict__ out,
                    int B, int V, int K)
{
    __shared__ float sWs[NTHREADS / 32];
    __shared__ int   sLast;
    __shared__ unsigned long long sCand[CAP];
    __shared__ uint32_t sKey[TOPN];
    __shared__ int      sIdx[TOPN];
    __shared__ float    sP[TOPN];
    __shared__ float    sS;
    __shared__ int      sNsh;

    const int tid   = threadIdx.x;
    const int lane  = tid & 31;
    const int wid   = tid >> 5;
    const int row   = blockIdx.x / SPLITS;
    const int split = blockIdx.x % SPLITS;

    const float* rowp = logits + (long long)row * V;

    // ---------------- streaming pass over this CTA's chunk -------------------
    int chunk = (((V + SPLITS - 1) / SPLITS) + 3) & ~3;   // multiple of 4
    int start = split * chunk;
    int end   = start + chunk; if (end > V) end = V;
    if (start > end) start = end;

    const float4* r4 = reinterpret_cast<const float4*>(rowp);
    const int s4 = start >> 2;
    const int e4 = end   >> 2;

    float a0 = 0.f, a1 = 0.f, a2 = 0.f, a3 = 0.f;
    int vi = s4 + tid;
    for (; vi + 3 * NTHREADS < e4; vi += 4 * NTHREADS) {
        float4 x0 = r4[vi];
        float4 x1 = r4[vi +     NTHREADS];
        float4 x2 = r4[vi + 2 * NTHREADS];
        float4 x3 = r4[vi + 3 * NTHREADS];

        a0 += __expf(x0.x); a1 += __expf(x0.y); a2 += __expf(x0.z); a3 += __expf(x0.w);
        a0 += __expf(x1.x); a1 += __expf(x1.y); a2 += __expf(x1.z); a3 += __expf(x1.w);
        a0 += __expf(x2.x); a1 += __expf(x2.y); a2 += __expf(x2.z); a3 += __expf(x2.w);
        a0 += __expf(x3.x); a1 += __expf(x3.y); a2 += __expf(x3.z); a3 += __expf(x3.w);

        collect4g(x0,  vi                 << 2, T_INIT, row);
        collect4g(x1, (vi +     NTHREADS) << 2, T_INIT, row);
        collect4g(x2, (vi + 2 * NTHREADS) << 2, T_INIT, row);
        collect4g(x3, (vi + 3 * NTHREADS) << 2, T_INIT, row);
    }
    for (; vi < e4; vi += NTHREADS) {
        float4 x0 = r4[vi];
        a0 += __expf(x0.x); a1 += __expf(x0.y); a2 += __expf(x0.z); a3 += __expf(x0.w);
        collect4g(x0, vi << 2, T_INIT, row);
    }
    for (int i = (e4 << 2) + tid; i < end; i += NTHREADS) {
        float x = rowp[i];
        a0 += __expf(x);
        if (x >= T_INIT) pushg(x, i, row);
    }

    float s = (a0 + a1) + (a2 + a3);
    #pragma unroll
    for (int off = 16; off; off >>= 1)
        s += __shfl_xor_sync(0xffffffffu, s, off);
    if (lane == 0) sWs[wid] = s;
    __syncthreads();

    // ---------------- publish partial; last CTA of the row finishes ----------
    if (tid == 0) {
        float S = 0.f;
        #pragma unroll
        for (int w = 0; w < NTHREADS / 32; w++) S += sWs[w];
        gPart[row * SPLITS + split] = S;
        __threadfence();                           // release: gPart/gCand visible
        int prev = atomicAdd(&gDone[row], 1);
        sLast = (prev == SPLITS - 1) ? 1 : 0;
    }
    __syncthreads();
    if (!sLast) return;

    // =================== FINISHER (one CTA per row) ==========================
    __threadfence();                               // acquire side
    if (tid == 0) {
        float S = 0.f;
        #pragma unroll
        for (int p = 0; p < SPLITS; p++) S += gPart[row * SPLITS + p];
        sS = S;
        sNsh = atomicAdd(&gCnt[row], 0);
    }
    __syncthreads();
    int n = sNsh;

    // ---- deterministic fallback rescan (never taken for this data) ----
    float T = T_INIT;
    for (int att = 0; att < 8 && (n < TOPN || n > CAP); att++) {
        T = (n < TOPN) ? (T - 1.5f) : (T + 1.25f);
        __syncthreads();
        if (tid == 0) gCnt[row] = 0;
        __syncthreads();
        const int nvec = V >> 2;
        for (int v2 = tid; v2 < nvec; v2 += NTHREADS)
            collect4g(r4[v2], v2 << 2, T, row);
        for (int i = (nvec << 2) + tid; i < V; i += NTHREADS) {
            float x = rowp[i];
            if (x >= T) pushg(x, i, row);
        }
        __syncthreads();
        if (tid == 0) sNsh = gCnt[row];
        __syncthreads();
        n = sNsh;
    }
    if (n > CAP) n = CAP;

    // ---- stage candidates in shared ----
    for (int i = tid; i < n; i += NTHREADS)
        sCand[i] = gCand[row * CAP + i];
    if (tid < TOPN) { sKey[tid] = 0u; sIdx[tid] = 0; }
    __syncthreads();

    // ---- exact rank (value desc, index asc via ~idx in low bits) ----
    for (int i = tid; i < n; i += NTHREADS) {
        unsigned long long mine = sCand[i];
        int rnk = 0;
        for (int j = 0; j < n; j++) rnk += (sCand[j] > mine) ? 1 : 0;
        if (rnk < TOPN) {
            sKey[rnk] = (uint32_t)(mine >> 32);
            sIdx[rnk] = (int)(~(uint32_t)mine);
        }
    }
    __syncthreads();

    // ---- top-K outputs + parallel prob precompute ----
    const float S = sS;
    if (tid < TOPN)
        sP[tid] = __expf(key2f(sKey[tid])) / S;
    if (tid < K) {
        float logZ = logf(S);
        out[B + (long long)row * K + tid] = key2f(sKey[tid]) - logZ;
        out[B + (long long)B * K + (long long)row * K + tid] = (float)sIdx[tid];
    }
    __syncthreads();

    // ---- serial sampling epilogue; no local array (values recomputed) -------
    if (tid == 0) {
        int   topk = top_ks[row];
        float tp = top_ps[row];
        float mp = min_ps[row];
        float uu = uvec[row];

        // loop 1: total + min-p threshold (exclusive-cumsum keep rule)
        float cum = 0.f, total = 0.f, thresh = 0.f;
        #pragma unroll 1
        for (int j = 0; j < TOPN; j++) {
            float p = sP[j];
            bool keep = (j < topk) && (cum <= tp);
            cum += p;
            if (j == 0) thresh = p * mp;
            float mj = keep ? p : 0.f;
            if (mj < thresh) mj = 0.f;
            total += mj;
        }
        // loop 2: recompute identical masked values; count cdf < target
        float target = uu * total;
        float cdf = 0.f;
        int pos = 0;
        cum = 0.f;
        #pragma unroll 1
        for (int j = 0; j < TOPN; j++) {
            float p = sP[j];
            bool keep = (j < topk) && (cum <= tp);
            cum += p;
            float mj = keep ? p : 0.f;
            if (mj < thresh) mj = 0.f;
            cdf += mj;
            pos += (cdf < target) ? 1 : 0;
        }
        if (pos > TOPN - 1) pos = TOPN - 1;
        out[row] = (float)sIdx[pos];

        // restore invariants for the next (graph-replayed) launch
        gCnt[row]  = 0;
        gDone[row] = 0;
    }
}

extern "C" void kernel_launch(void* const* d_in, const int* in_sizes, int n_in,
                              void* d_out, int out_size) {
    const float* logits = (const float*)d_in[0];
    const int*   top_ks = (const int*)d_in[1];
    const float* top_ps = (const float*)d_in[2];
    const float* min_ps = (const float*)d_in[3];
    const float* u      = (const float*)d_in[4];

    int B = in_sizes[1];
    int V = in_sizes[0] / B;
    int K = (out_size - B) / (2 * B);

    sampler_kernel<<<B * SPLITS, NTHREADS>>>(logits, top_ks, top_ps, min_ps, u,
                                             (float*)d_out, B, V, K);
}

// round 11
// speedup vs baseline: 1.3043x; 1.3043x over previous
#include <cuda_runtime.h>
#include <cstdint>

#define THREADS 1024
#define NWARPS  (THREADS / 32)
#define TOPN    64
#define CANDCAP 4096
#define T_INIT  6.0f

__device__ __forceinline__ uint32_t f2key(float x) {
    uint32_t u = __float_as_uint(x);
    return (u & 0x80000000u) ? ~u : (u | 0x80000000u);
}
__device__ __forceinline__ float key2f(uint32_t k) {
    uint32_t u = (k & 0x80000000u) ? (k & 0x7FFFFFFFu) : ~k;
    return __uint_as_float(u);
}
__device__ __forceinline__ float max4(float4 x) {
    return fmaxf(fmaxf(x.x, x.y), fmaxf(x.z, x.w));
}

__device__ __forceinline__ void push1(float v, int idx, int* sN,
                                      unsigned long long* sCand) {
    int p = atomicAdd(sN, 1);
    if (p < CANDCAP)
        sCand[p] = ((unsigned long long)f2key(v) << 32) | (uint32_t)(~(uint32_t)idx);
}
__device__ __forceinline__ void collect4(float4 x, int base, float T, int* sN,
                                         unsigned long long* sCand) {
    if (max4(x) >= T) {   // rarely taken (~0.5% of float4s)
        if (x.x >= T) push1(x.x, base + 0, sN, sCand);
        if (x.y >= T) push1(x.y, base + 1, sN, sCand);
        if (x.z >= T) push1(x.z, base + 2, sN, sCand);
        if (x.w >= T) push1(x.w, base + 3, sN, sCand);
    }
}

__global__ __launch_bounds__(THREADS, 1)
void sampler_kernel(const float* __restrict__ logits,
                    const int*   __restrict__ top_ks,
                    const float* __restrict__ top_ps,
                    const float* __restrict__ min_ps,
                    const float* __restrict__ uvec,
                    float* __restrict__ out,
                    int B, int V, int K)
{
    __shared__ float sWs[NWARPS];
    __shared__ float sS;
    __shared__ int sN;
    __shared__ unsigned long long sCand[CANDCAP];
    __shared__ uint32_t sKey[TOPN];
    __shared__ int      sIdx[TOPN];
    __shared__ float    sP[TOPN];

    const int tid  = threadIdx.x;
    const int lane = tid & 31;
    const int wid  = tid >> 5;
    const int row  = blockIdx.x;

    const float*  rowp = logits + (long long)row * V;
    const float4* r4   = reinterpret_cast<const float4*>(rowp);
    const int nvec = V >> 2;

    if (tid == 0) sN = 0;
    __syncthreads();

    // ===== SINGLE DRAM pass, software-pipelined (prefetch next batch) ========
    float a0 = 0.f, a1 = 0.f, a2 = 0.f, a3 = 0.f;

    int vi = tid;
    if (vi + 3 * THREADS < nvec) {
        // preload first batch
        float4 x0 = r4[vi];
        float4 x1 = r4[vi +     THREADS];
        float4 x2 = r4[vi + 2 * THREADS];
        float4 x3 = r4[vi + 3 * THREADS];
        int cur = vi;
        vi += 4 * THREADS;

        for (; vi + 3 * THREADS < nvec; vi += 4 * THREADS) {
            // prefetch next batch BEFORE consuming current one
            float4 y0 = r4[vi];
            float4 y1 = r4[vi +     THREADS];
            float4 y2 = r4[vi + 2 * THREADS];
            float4 y3 = r4[vi + 3 * THREADS];

            a0 += __expf(x0.x); a1 += __expf(x0.y); a2 += __expf(x0.z); a3 += __expf(x0.w);
            a0 += __expf(x1.x); a1 += __expf(x1.y); a2 += __expf(x1.z); a3 += __expf(x1.w);
            a0 += __expf(x2.x); a1 += __expf(x2.y); a2 += __expf(x2.z); a3 += __expf(x2.w);
            a0 += __expf(x3.x); a1 += __expf(x3.y); a2 += __expf(x3.z); a3 += __expf(x3.w);

            collect4(x0,  cur                << 2, T_INIT, &sN, sCand);
            collect4(x1, (cur +     THREADS) << 2, T_INIT, &sN, sCand);
            collect4(x2, (cur + 2 * THREADS) << 2, T_INIT, &sN, sCand);
            collect4(x3, (cur + 3 * THREADS) << 2, T_INIT, &sN, sCand);

            x0 = y0; x1 = y1; x2 = y2; x3 = y3;
            cur = vi;
        }

        // drain last full batch
        a0 += __expf(x0.x); a1 += __expf(x0.y); a2 += __expf(x0.z); a3 += __expf(x0.w);
        a0 += __expf(x1.x); a1 += __expf(x1.y); a2 += __expf(x1.z); a3 += __expf(x1.w);
        a0 += __expf(x2.x); a1 += __expf(x2.y); a2 += __expf(x2.z); a3 += __expf(x2.w);
        a0 += __expf(x3.x); a1 += __expf(x3.y); a2 += __expf(x3.z); a3 += __expf(x3.w);
        collect4(x0,  cur                << 2, T_INIT, &sN, sCand);
        collect4(x1, (cur +     THREADS) << 2, T_INIT, &sN, sCand);
        collect4(x2, (cur + 2 * THREADS) << 2, T_INIT, &sN, sCand);
        collect4(x3, (cur + 3 * THREADS) << 2, T_INIT, &sN, sCand);
    }
    for (; vi < nvec; vi += THREADS) {
        float4 x = r4[vi];
        a0 += __expf(x.x); a1 += __expf(x.y); a2 += __expf(x.z); a3 += __expf(x.w);
        collect4(x, vi << 2, T_INIT, &sN, sCand);
    }
    for (int i = (nvec << 2) + tid; i < V; i += THREADS) {
        float x = rowp[i];
        a0 += __expf(x);
        if (x >= T_INIT) push1(x, i, &sN, sCand);
    }

    // ---- block reduce sum(exp) ----
    float s = (a0 + a1) + (a2 + a3);
    #pragma unroll
    for (int off = 16; off; off >>= 1)
        s += __shfl_xor_sync(0xffffffffu, s, off);
    if (lane == 0) sWs[wid] = s;
    __syncthreads();
    if (tid == 0) {
        float S = 0.f;
        #pragma unroll
        for (int w = 0; w < NWARPS; w++) S += sWs[w];
        sS = S;
    }
    __syncthreads();

    // ---- deterministic fallback rescan (never taken for this data) ----
    int n = sN;
    float T = T_INIT;
    for (int att = 0; att < 8 && (n < TOPN || n > CANDCAP); att++) {
        T = (n < TOPN) ? (T - 1.5f) : (T + 1.25f);
        __syncthreads();
        if (tid == 0) sN = 0;
        __syncthreads();
        for (int v2 = tid; v2 < nvec; v2 += THREADS)
            collect4(r4[v2], v2 << 2, T, &sN, sCand);
        for (int i = (nvec << 2) + tid; i < V; i += THREADS) {
            float x = rowp[i];
            if (x >= T) push1(x, i, &sN, sCand);
        }
        __syncthreads();
        n = sN;
    }
    if (n > CANDCAP) n = CANDCAP;

    // ---- exact rank among candidates (value desc, index asc on ties) ----
    for (int i = tid; i < n; i += THREADS) {
        unsigned long long mine = sCand[i];
        int rnk = 0;
        for (int j = 0; j < n; j++) rnk += (sCand[j] > mine) ? 1 : 0;
        if (rnk < TOPN) {
            sKey[rnk] = (uint32_t)(mine >> 32);
            sIdx[rnk] = (int)(~(uint32_t)mine);
        }
    }
    __syncthreads();

    // ---- parallel prob precompute + top-K outputs ----
    const float S = sS;
    if (tid < TOPN)
        sP[tid] = __expf(key2f(sKey[tid])) / S;
    if (tid < K) {
        float logZ = logf(S);
        out[B + (long long)row * K + tid] = key2f(sKey[tid]) - logZ;
        out[B + (long long)B * K + (long long)row * K + tid] = (float)sIdx[tid];
    }
    __syncthreads();

    // ---- serial sampling epilogue (reference's prefix-cumsum semantics) ----
    if (tid == 0) {
        int   topk = top_ks[row];
        float tp = top_ps[row];
        float mp = min_ps[row];
        float uu = uvec[row];

        // loop 1: min-p threshold + masked total (exclusive-cumsum keep rule)
        float cum = 0.f, total = 0.f, thresh = 0.f;
        #pragma unroll 1
        for (int j = 0; j < TOPN; j++) {
            float p = sP[j];
            bool keep = (j < topk) && (cum <= tp);
            cum += p;
            if (j == 0) thresh = p * mp;
            float mj = keep ? p : 0.f;
            if (mj < thresh) mj = 0.f;
            total += mj;
        }
        // loop 2: recompute identical masked values; count cdf < target
        float target = uu * total;
        float cdf = 0.f;
        int pos = 0;
        cum = 0.f;
        #pragma unroll 1
        for (int j = 0; j < TOPN; j++) {
            float p = sP[j];
            bool keep = (j < topk) && (cum <= tp);
            cum += p;
            float mj = keep ? p : 0.f;
            if (mj < thresh) mj = 0.f;
            cdf += mj;
            pos += (cdf < target) ? 1 : 0;
        }
        if (pos > TOPN - 1) pos = TOPN - 1;
        out[row] = (float)sIdx[pos];
    }
}

extern "C" void kernel_launch(void* const* d_in, const int* in_sizes, int n_in,
                              void* d_out, int out_size) {
    const float* logits = (const float*)d_in[0];
    const int*   top_ks = (const int*)d_in[1];
    const float* top_ps = (const float*)d_in[2];
    const float* min_ps = (const float*)d_in[3];
    const float* u      = (const float*)d_in[4];

    int B = in_sizes[1];
    int V = in_sizes[0] / B;
    int K = (out_size - B) / (2 * B);

    sampler_kernel<<<B, THREADS>>>(logits, top_ks, top_ps, min_ps, u,
                                   (float*)d_out, B, V, K);
}